// round 7
// baseline (speedup 1.0000x reference)
#include <cuda_runtime.h>
#include <cuda_bf16.h>
#include <cstdint>

// ---------------- problem constants ----------------
#define BN      4096
#define KN      20
#define D_EMB   128
#define D_FEAT  172
#define D_TIME  100
#define XCOLS   448              // X row stride: node 172 | edge 172 | time 100 | pad 4
#define KTOT    448
#define GROWS   8                // GEMM rows per block
#define XS_ST   10               // xs k-stride (floats): even -> 8B-aligned row pairs
#define WCHUNK  8                // k per W smem chunk
#define NCHUNK  (KTOT / WCHUNK)  // 56
#define XS_FLOATS (KTOT * XS_ST)             // 4480
#define WS_FLOATS (2 * WCHUNK * D_EMB)       // 2048
#define GSMEM_BYTES ((XS_FLOATS + WS_FLOATS) * 4)   // 26112

typedef unsigned long long ull;

// ---------------- device scratch (no allocation allowed) ----------------
__device__ __align__(16) float g_X[(size_t)BN * XCOLS];     // 7.3 MB reduced features
__device__ __align__(16) float g_base[(size_t)BN * D_EMB];  // memory terms
__device__ __align__(16) float g_W[(size_t)KTOT * D_EMB];   // packed [Wn;We;Wt;0]

// ---------------- accurate cos for large fp32 args (validated) ----------------
__device__ __forceinline__ float cos_cw(float x) {
    const float TWO_OVER_PI = 0.63661977236758134f;
    const float P1 = 1.57079625129699707031e+00f;
    const float P2 = 7.54978941586159375e-08f;
    const float P3 = 5.39030252995776477e-15f;
    float n = rintf(x * TWO_OVER_PI);
    float r = fmaf(n, -P1, x);
    r = fmaf(n, -P2, r);
    r = fmaf(n, -P3, r);
    int q = ((int)n) & 3;
    float r2 = r * r;
    float s = fmaf(r2, -1.98412698412698413e-4f, 8.33333333333333322e-3f);
    s = fmaf(r2, s, -1.66666666666666666e-1f);
    s = r * fmaf(r2, s, 1.0f);
    float c = fmaf(r2, 2.48015873015873016e-5f, -1.38888888888888889e-3f);
    c = fmaf(r2, c, 4.16666666666666666e-2f);
    c = fmaf(r2, c, -0.5f);
    c = fmaf(r2, c, 1.0f);
    float v = (q & 1) ? s : c;
    if ((q + 1) & 2) v = -v;
    return v;
}

// ---------------- f32x2 packed helpers ----------------
__device__ __forceinline__ ull dup2(float v) {
    ull r;
    asm("mov.b64 %0, {%1, %1};" : "=l"(r) : "f"(v));
    return r;
}
__device__ __forceinline__ void fma2(ull& d, ull a, ull b) {
    asm("fma.rn.f32x2 %0, %1, %2, %0;" : "+l"(d) : "l"(a), "l"(b));
}
__device__ __forceinline__ void unpack2(ull v, float& lo, float& hi) {
    asm("mov.b64 {%0, %1}, %2;" : "=f"(lo), "=f"(hi) : "l"(v));
}

// ---------------- gather v2: float4 gathers + concurrent cos tasks (validated) ----------------
// Tasks: t<43 node float4 | t<86 edge float4 | t<118 mem float4 | t<218 time scalar | t<222 pad
__global__ void __launch_bounds__(256) gather_kernel(
    const float* __restrict__ nf, const float* __restrict__ ef,
    const float* __restrict__ mem,
    const float* __restrict__ ts, const float* __restrict__ ets,
    const float* __restrict__ tw, const float* __restrict__ tb,
    const int* __restrict__ srcn, const int* __restrict__ nbr,
    const int* __restrict__ eidx,
    const float* __restrict__ W_node, const float* __restrict__ W_edge,
    const float* __restrict__ W_time)
{
    const int b = blockIdx.x;
    const int t = threadIdx.x;

    // ---- W pack side-job on first 224 blocks (no extra launch) ----
    if (b < (KTOT * D_EMB) / 256) {
        const int i = b * 256 + t;
        const int k = i >> 7;
        const int n = i & 127;
        float v;
        if (k < D_FEAT)                   v = W_node[k * D_EMB + n];
        else if (k < 2 * D_FEAT)          v = W_edge[(k - D_FEAT) * D_EMB + n];
        else if (k < 2 * D_FEAT + D_TIME) v = W_time[(k - 2 * D_FEAT) * D_EMB + n];
        else                              v = 0.f;
        g_W[i] = v;
    }

    __shared__ int   nbr_s[KN];
    __shared__ int   eidx_s[KN];
    __shared__ float del_s[KN];
    __shared__ float msk_s[KN];

    if (t < KN) {
        int nb = nbr[b * KN + t];
        nbr_s[t]  = nb;
        eidx_s[t] = eidx[b * KN + t];
        del_s[t]  = ts[b] - ets[b * KN + t];
        msk_s[t]  = (nb != 0) ? 1.f : 0.f;
    }
    __syncthreads();

    float cntf = 0.f;
    #pragma unroll
    for (int k = 0; k < KN; k++) cntf += msk_s[k];
    const float inv = 1.f / fmaxf(cntf, 1.f);
    const int src = srcn[b];

    if (t < 118) {
        const bool is_node = (t < 43);
        const bool is_edge = (t >= 43 && t < 86);
        const float* bp;
        int stride, colo;
        const int* rs;
        if (is_node)      { bp = nf;  stride = D_FEAT; colo = 4 * t;        rs = nbr_s; }
        else if (is_edge) { bp = ef;  stride = D_FEAT; colo = 4 * (t - 43); rs = eidx_s; }
        else              { bp = mem; stride = D_EMB;  colo = 4 * (t - 86); rs = nbr_s; }

        float4 acc = make_float4(0.f, 0.f, 0.f, 0.f);
        #pragma unroll
        for (int k = 0; k < KN; k++) {
            const float m = msk_s[k];
            const float4 v = __ldg((const float4*)(bp + (size_t)rs[k] * stride + colo));
            acc.x = fmaf(m, v.x, acc.x);
            acc.y = fmaf(m, v.y, acc.y);
            acc.z = fmaf(m, v.z, acc.z);
            acc.w = fmaf(m, v.w, acc.w);
        }
        acc.x *= inv; acc.y *= inv; acc.z *= inv; acc.w *= inv;

        if (is_node) {
            const float4 sv = __ldg((const float4*)(nf + (size_t)src * D_FEAT + colo));
            acc.x += sv.x; acc.y += sv.y; acc.z += sv.z; acc.w += sv.w;
            *(float4*)&g_X[(size_t)b * XCOLS + colo] = acc;
        } else if (is_edge) {
            *(float4*)&g_X[(size_t)b * XCOLS + D_FEAT + colo] = acc;
        } else {
            const float4 sv = __ldg((const float4*)(mem + (size_t)src * D_EMB + colo));
            acc.x += sv.x; acc.y += sv.y; acc.z += sv.z; acc.w += sv.w;
            *(float4*)&g_base[(size_t)b * D_EMB + colo] = acc;
        }
    } else if (t < 218) {
        const int j = t - 118;
        const float wj = tw[j];
        const float bj = tb[j];
        float a = 0.f;
        #pragma unroll
        for (int k = 0; k < KN; k++) {
            float v = cos_cw(__fadd_rn(__fmul_rn(del_s[k], wj), bj));
            a = fmaf(msk_s[k], v, a);
        }
        g_X[(size_t)b * XCOLS + 344 + j] = a * inv + cos_cw(bj);
    } else if (t < 222) {
        g_X[(size_t)b * XCOLS + 444 + (t - 218)] = 0.f;   // pad cols
    }
}

// ---------------- f32x2 GEMM v5: 8 rows/block, grid 512, ~3.5 CTAs/SM ----------------
// warp w owns row-pair (m0+2w, m0+2w+1); lane covers cols [4*lane, 4*lane+4).
__global__ void __launch_bounds__(128) gemm_kernel(float* __restrict__ out)
{
    extern __shared__ float sm[];
    float* xs = sm;                    // [KTOT][XS_ST] transposed X tile
    float* ws = sm + XS_FLOATS;        // double-buffered W chunks [2][WCHUNK*128]

    const int tid = threadIdx.x;
    const int wid = tid >> 5;
    const int lane = tid & 31;
    const int c0 = lane * 4;
    const int rp = 2 * wid;            // row-pair base within tile
    const int m0 = blockIdx.x * GROWS;

    // ---- fill transposed X tile (coalesced LDG.128, strided STS) ----
    for (int idx = tid; idx < GROWS * (XCOLS / 4); idx += 128) {
        const int row = idx / (XCOLS / 4);
        const int c4 = idx - row * (XCOLS / 4);
        float4 x = *(const float4*)&g_X[(size_t)(m0 + row) * XCOLS + c4 * 4];
        const int kb = c4 * 4;
        xs[(kb + 0) * XS_ST + row] = x.x;
        xs[(kb + 1) * XS_ST + row] = x.y;
        xs[(kb + 2) * XS_ST + row] = x.z;
        xs[(kb + 3) * XS_ST + row] = x.w;
    }

    // ---- prologue: W chunk 0 -> regs -> buf 0 (2 float4 per thread) ----
    const float4* W4 = (const float4*)g_W;
    float4 p0 = W4[tid];
    float4 p1 = W4[tid + 128];
    {
        float4* w0 = (float4*)ws;
        w0[tid] = p0;
        w0[tid + 128] = p1;
    }
    __syncthreads();

    ull acc0 = 0ULL, acc1 = 0ULL, acc2 = 0ULL, acc3 = 0ULL;

    #pragma unroll 1
    for (int c = 0; c < NCHUNK; c++) {
        if (c + 1 < NCHUNK) {
            const int base = (c + 1) * (WCHUNK * D_EMB / 4);
            p0 = W4[base + tid];
            p1 = W4[base + tid + 128];
        }
        const float* wc = ws + (c & 1) * (WCHUNK * D_EMB);
        const int k0 = c * WCHUNK;
        #pragma unroll
        for (int i = 0; i < WCHUNK; i++) {
            const float4 wv = *(const float4*)&wc[i * D_EMB + c0];
            ull x2 = *(const ull*)&xs[(k0 + i) * XS_ST + rp];   // broadcast LDS.64
            fma2(acc0, x2, dup2(wv.x));
            fma2(acc1, x2, dup2(wv.y));
            fma2(acc2, x2, dup2(wv.z));
            fma2(acc3, x2, dup2(wv.w));
        }
        if (c + 1 < NCHUNK) {
            float4* wn = (float4*)(ws + ((c + 1) & 1) * (WCHUNK * D_EMB));
            wn[tid] = p0;
            wn[tid + 128] = p1;
        }
        __syncthreads();
    }

    // ---- epilogue: unpack, add base, store ----
    float l0, h0, l1, h1, l2, h2, l3, h3;
    unpack2(acc0, l0, h0);
    unpack2(acc1, l1, h1);
    unpack2(acc2, l2, h2);
    unpack2(acc3, l3, h3);
    const size_t rA = (size_t)(m0 + rp) * D_EMB + c0;
    const size_t rB = rA + D_EMB;
    float4 bA = *(const float4*)&g_base[rA];
    float4 bB = *(const float4*)&g_base[rB];
    *(float4*)&out[rA] = make_float4(l0 + bA.x, l1 + bA.y, l2 + bA.z, l3 + bA.w);
    *(float4*)&out[rB] = make_float4(h0 + bB.x, h1 + bB.y, h2 + bB.z, h3 + bB.w);
}

extern "C" void kernel_launch(void* const* d_in, const int* in_sizes, int n_in,
                              void* d_out, int out_size) {
    const float* node_features = (const float*)d_in[0];
    const float* edge_features = (const float*)d_in[1];
    const float* memory        = (const float*)d_in[2];
    const float* timestamps    = (const float*)d_in[3];
    const float* edge_times    = (const float*)d_in[4];
    const float* time_w        = (const float*)d_in[5];
    const float* time_b        = (const float*)d_in[6];
    const float* W_node        = (const float*)d_in[7];
    const float* W_edge        = (const float*)d_in[8];
    const float* W_time        = (const float*)d_in[9];
    const int*   source_nodes  = (const int*)d_in[10];
    const int*   neighbors     = (const int*)d_in[11];
    const int*   edge_idxs     = (const int*)d_in[12];
    float* out = (float*)d_out;

    gather_kernel<<<BN, 256>>>(node_features, edge_features, memory,
                               timestamps, edge_times, time_w, time_b,
                               source_nodes, neighbors, edge_idxs,
                               W_node, W_edge, W_time);
    gemm_kernel<<<BN / GROWS, 128, GSMEM_BYTES>>>(out);
}

// round 8
// speedup vs baseline: 1.0142x; 1.0142x over previous
#include <cuda_runtime.h>
#include <cuda_bf16.h>
#include <cstdint>

// ---------------- problem constants ----------------
#define BN      4096
#define KN      20
#define D_EMB   128
#define D_FEAT  172
#define D_TIME  100
#define XCOLS   448              // X row stride: node 172 | edge 172 | time 100 | pad 4
#define KTOT    448
#define GROWS   8                // GEMM rows per block
#define XS_ST   12               // xs k-stride: rows 0-3 / 4-7 are 16B-aligned quads
#define GSMEM_BYTES (KTOT * XS_ST * 4)   // 21504

typedef unsigned long long ull;

// ---------------- device scratch (no allocation allowed) ----------------
__device__ __align__(16) float g_X[(size_t)BN * XCOLS];     // 7.3 MB reduced features
__device__ __align__(16) float g_base[(size_t)BN * D_EMB];  // memory terms
__device__ __align__(16) float g_W[(size_t)KTOT * D_EMB];   // packed [Wn;We;Wt;0]

// ---------------- accurate cos for large fp32 args (validated) ----------------
__device__ __forceinline__ float cos_cw(float x) {
    const float TWO_OVER_PI = 0.63661977236758134f;
    const float P1 = 1.57079625129699707031e+00f;
    const float P2 = 7.54978941586159375e-08f;
    const float P3 = 5.39030252995776477e-15f;
    float n = rintf(x * TWO_OVER_PI);
    float r = fmaf(n, -P1, x);
    r = fmaf(n, -P2, r);
    r = fmaf(n, -P3, r);
    int q = ((int)n) & 3;
    float r2 = r * r;
    float s = fmaf(r2, -1.98412698412698413e-4f, 8.33333333333333322e-3f);
    s = fmaf(r2, s, -1.66666666666666666e-1f);
    s = r * fmaf(r2, s, 1.0f);
    float c = fmaf(r2, 2.48015873015873016e-5f, -1.38888888888888889e-3f);
    c = fmaf(r2, c, 4.16666666666666666e-2f);
    c = fmaf(r2, c, -0.5f);
    c = fmaf(r2, c, 1.0f);
    float v = (q & 1) ? s : c;
    if ((q + 1) & 2) v = -v;
    return v;
}

// ---------------- f32x2 packed helpers ----------------
__device__ __forceinline__ ull dup2(float v) {
    ull r;
    asm("mov.b64 %0, {%1, %1};" : "=l"(r) : "f"(v));
    return r;
}
__device__ __forceinline__ void fma2(ull& d, ull a, ull b) {
    asm("fma.rn.f32x2 %0, %1, %2, %0;" : "+l"(d) : "l"(a), "l"(b));
}
__device__ __forceinline__ void unpack2(ull v, float& lo, float& hi) {
    asm("mov.b64 {%0, %1}, %2;" : "=f"(lo), "=f"(hi) : "l"(v));
}

// ---------------- gather v2: float4 gathers + concurrent cos tasks (validated) ----------------
// Tasks: t<43 node float4 | t<86 edge float4 | t<118 mem float4 | t<218 time scalar | t<222 pad
__global__ void __launch_bounds__(256) gather_kernel(
    const float* __restrict__ nf, const float* __restrict__ ef,
    const float* __restrict__ mem,
    const float* __restrict__ ts, const float* __restrict__ ets,
    const float* __restrict__ tw, const float* __restrict__ tb,
    const int* __restrict__ srcn, const int* __restrict__ nbr,
    const int* __restrict__ eidx,
    const float* __restrict__ W_node, const float* __restrict__ W_edge,
    const float* __restrict__ W_time)
{
    const int b = blockIdx.x;
    const int t = threadIdx.x;

    // ---- W pack side-job on first 224 blocks (no extra launch) ----
    if (b < (KTOT * D_EMB) / 256) {
        const int i = b * 256 + t;
        const int k = i >> 7;
        const int n = i & 127;
        float v;
        if (k < D_FEAT)                   v = W_node[k * D_EMB + n];
        else if (k < 2 * D_FEAT)          v = W_edge[(k - D_FEAT) * D_EMB + n];
        else if (k < 2 * D_FEAT + D_TIME) v = W_time[(k - 2 * D_FEAT) * D_EMB + n];
        else                              v = 0.f;
        g_W[i] = v;
    }

    __shared__ int   nbr_s[KN];
    __shared__ int   eidx_s[KN];
    __shared__ float del_s[KN];
    __shared__ float msk_s[KN];

    if (t < KN) {
        int nb = nbr[b * KN + t];
        nbr_s[t]  = nb;
        eidx_s[t] = eidx[b * KN + t];
        del_s[t]  = ts[b] - ets[b * KN + t];
        msk_s[t]  = (nb != 0) ? 1.f : 0.f;
    }
    __syncthreads();

    float cntf = 0.f;
    #pragma unroll
    for (int k = 0; k < KN; k++) cntf += msk_s[k];
    const float inv = 1.f / fmaxf(cntf, 1.f);
    const int src = srcn[b];

    if (t < 118) {
        const bool is_node = (t < 43);
        const bool is_edge = (t >= 43 && t < 86);
        const float* bp;
        int stride, colo;
        const int* rs;
        if (is_node)      { bp = nf;  stride = D_FEAT; colo = 4 * t;        rs = nbr_s; }
        else if (is_edge) { bp = ef;  stride = D_FEAT; colo = 4 * (t - 43); rs = eidx_s; }
        else              { bp = mem; stride = D_EMB;  colo = 4 * (t - 86); rs = nbr_s; }

        float4 acc = make_float4(0.f, 0.f, 0.f, 0.f);
        #pragma unroll
        for (int k = 0; k < KN; k++) {
            const float m = msk_s[k];
            const float4 v = __ldg((const float4*)(bp + (size_t)rs[k] * stride + colo));
            acc.x = fmaf(m, v.x, acc.x);
            acc.y = fmaf(m, v.y, acc.y);
            acc.z = fmaf(m, v.z, acc.z);
            acc.w = fmaf(m, v.w, acc.w);
        }
        acc.x *= inv; acc.y *= inv; acc.z *= inv; acc.w *= inv;

        if (is_node) {
            const float4 sv = __ldg((const float4*)(nf + (size_t)src * D_FEAT + colo));
            acc.x += sv.x; acc.y += sv.y; acc.z += sv.z; acc.w += sv.w;
            *(float4*)&g_X[(size_t)b * XCOLS + colo] = acc;
        } else if (is_edge) {
            *(float4*)&g_X[(size_t)b * XCOLS + D_FEAT + colo] = acc;
        } else {
            const float4 sv = __ldg((const float4*)(mem + (size_t)src * D_EMB + colo));
            acc.x += sv.x; acc.y += sv.y; acc.z += sv.z; acc.w += sv.w;
            *(float4*)&g_base[(size_t)b * D_EMB + colo] = acc;
        }
    } else if (t < 218) {
        const int j = t - 118;
        const float wj = tw[j];
        const float bj = tb[j];
        float a = 0.f;
        #pragma unroll
        for (int k = 0; k < KN; k++) {
            float v = cos_cw(__fadd_rn(__fmul_rn(del_s[k], wj), bj));
            a = fmaf(msk_s[k], v, a);
        }
        g_X[(size_t)b * XCOLS + 344 + j] = a * inv + cos_cw(bj);
    } else if (t < 222) {
        g_X[(size_t)b * XCOLS + 444 + (t - 218)] = 0.f;   // pad cols
    }
}

// ---------------- f32x2 GEMM v6: lane-per-column, W via coalesced LDG (L2) ----------------
// grid 512 x 128 thr. Lane owns col = wid*32 + lane; block owns 8 rows (4 f32x2 pairs).
// Per k: 2 broadcast LDS.128 (rows 0-3, 4-7) + 1 dup2 + 4 fma2; W batched 8-deep LDG.32.
__global__ void __launch_bounds__(128) gemm_kernel(float* __restrict__ out)
{
    __shared__ float xs[KTOT * XS_ST];   // 21.5 KB transposed X tile
    const int tid = threadIdx.x;
    const int col = tid;                 // wid*32 + lane == tid
    const int m0 = blockIdx.x * GROWS;

    // ---- fill transposed X tile (coalesced LDG.128, strided STS) ----
    for (int idx = tid; idx < GROWS * (XCOLS / 4); idx += 128) {
        const int row = idx / (XCOLS / 4);
        const int c4 = idx - row * (XCOLS / 4);
        float4 x = *(const float4*)&g_X[(size_t)(m0 + row) * XCOLS + c4 * 4];
        const int kb = c4 * 4;
        xs[(kb + 0) * XS_ST + row] = x.x;
        xs[(kb + 1) * XS_ST + row] = x.y;
        xs[(kb + 2) * XS_ST + row] = x.z;
        xs[(kb + 3) * XS_ST + row] = x.w;
    }
    __syncthreads();

    ull acc0 = 0ULL, acc1 = 0ULL, acc2 = 0ULL, acc3 = 0ULL;

    #pragma unroll 1
    for (int kb = 0; kb < KTOT; kb += 8) {
        // batch 8 W loads (coalesced LDG.32, L2-resident, MLP=8)
        float w[8];
        #pragma unroll
        for (int i = 0; i < 8; i++)
            w[i] = __ldg(&g_W[(size_t)(kb + i) * D_EMB + col]);
        #pragma unroll
        for (int i = 0; i < 8; i++) {
            const float* xk = &xs[(kb + i) * XS_ST];
            const float4 xa = *(const float4*)xk;         // rows 0-3 (broadcast LDS.128)
            const float4 xb = *(const float4*)(xk + 4);   // rows 4-7 (broadcast LDS.128)
            const ull w2 = dup2(w[i]);
            ull x01, x23, x45, x67;
            asm("mov.b64 %0, {%1, %2};" : "=l"(x01) : "f"(xa.x), "f"(xa.y));
            asm("mov.b64 %0, {%1, %2};" : "=l"(x23) : "f"(xa.z), "f"(xa.w));
            asm("mov.b64 %0, {%1, %2};" : "=l"(x45) : "f"(xb.x), "f"(xb.y));
            asm("mov.b64 %0, {%1, %2};" : "=l"(x67) : "f"(xb.z), "f"(xb.w));
            fma2(acc0, x01, w2);
            fma2(acc1, x23, w2);
            fma2(acc2, x45, w2);
            fma2(acc3, x67, w2);
        }
    }

    // ---- epilogue: unpack, add base, store (scalar, coalesced across lanes) ----
    float r[8];
    unpack2(acc0, r[0], r[1]);
    unpack2(acc1, r[2], r[3]);
    unpack2(acc2, r[4], r[5]);
    unpack2(acc3, r[6], r[7]);
    #pragma unroll
    for (int i = 0; i < 8; i++) {
        const size_t o = (size_t)(m0 + i) * D_EMB + col;
        out[o] = r[i] + __ldg(&g_base[o]);
    }
}

extern "C" void kernel_launch(void* const* d_in, const int* in_sizes, int n_in,
                              void* d_out, int out_size) {
    const float* node_features = (const float*)d_in[0];
    const float* edge_features = (const float*)d_in[1];
    const float* memory        = (const float*)d_in[2];
    const float* timestamps    = (const float*)d_in[3];
    const float* edge_times    = (const float*)d_in[4];
    const float* time_w        = (const float*)d_in[5];
    const float* time_b        = (const float*)d_in[6];
    const float* W_node        = (const float*)d_in[7];
    const float* W_edge        = (const float*)d_in[8];
    const float* W_time        = (const float*)d_in[9];
    const int*   source_nodes  = (const int*)d_in[10];
    const int*   neighbors     = (const int*)d_in[11];
    const int*   edge_idxs     = (const int*)d_in[12];
    float* out = (float*)d_out;

    gather_kernel<<<BN, 256>>>(node_features, edge_features, memory,
                               timestamps, edge_times, time_w, time_b,
                               source_nodes, neighbors, edge_idxs,
                               W_node, W_edge, W_time);
    gemm_kernel<<<BN / GROWS, 128>>>(out);
}

// round 9
// speedup vs baseline: 1.2290x; 1.2119x over previous
#include <cuda_runtime.h>
#include <cuda_bf16.h>
#include <cstdint>

// ---------------- problem constants ----------------
#define BN      4096
#define KN      20
#define D_EMB   128
#define D_FEAT  172
#define D_TIME  100
#define KTOT    444              // node 172 | edge 172 | time 100
#define GROWS   8                // batch rows per block
#define XS_ST   12               // xs k-stride: row pairs 8B-aligned
#define TPB     256
#define TASKS_PER_ROW 224        // 43 node-f4 | 43 edge-f4 | 32 mem-f4 | 100 cos | 6 pad
#define NTASKS  (GROWS * TASKS_PER_ROW)   // 1792

typedef unsigned long long ull;

// ---------------- accurate cos for large fp32 args (validated) ----------------
__device__ __forceinline__ float cos_cw(float x) {
    const float TWO_OVER_PI = 0.63661977236758134f;
    const float P1 = 1.57079625129699707031e+00f;
    const float P2 = 7.54978941586159375e-08f;
    const float P3 = 5.39030252995776477e-15f;
    float n = rintf(x * TWO_OVER_PI);
    float r = fmaf(n, -P1, x);
    r = fmaf(n, -P2, r);
    r = fmaf(n, -P3, r);
    int q = ((int)n) & 3;
    float r2 = r * r;
    float s = fmaf(r2, -1.98412698412698413e-4f, 8.33333333333333322e-3f);
    s = fmaf(r2, s, -1.66666666666666666e-1f);
    s = r * fmaf(r2, s, 1.0f);
    float c = fmaf(r2, 2.48015873015873016e-5f, -1.38888888888888889e-3f);
    c = fmaf(r2, c, 4.16666666666666666e-2f);
    c = fmaf(r2, c, -0.5f);
    c = fmaf(r2, c, 1.0f);
    float v = (q & 1) ? s : c;
    if ((q + 1) & 2) v = -v;
    return v;
}

// ---------------- f32x2 packed helpers ----------------
__device__ __forceinline__ ull dup2(float v) {
    ull r;
    asm("mov.b64 %0, {%1, %1};" : "=l"(r) : "f"(v));
    return r;
}
__device__ __forceinline__ void fma2(ull& d, ull a, ull b) {
    asm("fma.rn.f32x2 %0, %1, %2, %0;" : "+l"(d) : "l"(a), "l"(b));
}
__device__ __forceinline__ void unpack2(ull v, float& lo, float& hi) {
    asm("mov.b64 {%0, %1}, %2;" : "=f"(lo), "=f"(hi) : "l"(v));
}

// ---------------- fused gather + masked-mean + projection GEMM ----------------
// Block = 8 batch rows. Phase 1: gather/reduce X tile (transposed in smem) + base.
// Phase 2: lane-per-column f32x2 GEMM, W streamed from original arrays via L2.
__global__ void __launch_bounds__(TPB) fused_kernel(
    const float* __restrict__ nf, const float* __restrict__ ef,
    const float* __restrict__ mem,
    const float* __restrict__ ts, const float* __restrict__ ets,
    const float* __restrict__ tw, const float* __restrict__ tb,
    const int* __restrict__ srcn, const int* __restrict__ nbr,
    const int* __restrict__ eidx,
    const float* __restrict__ W_node, const float* __restrict__ W_edge,
    const float* __restrict__ W_time,
    float* __restrict__ out)
{
    __shared__ float xs[KTOT * XS_ST];        // 21312 B transposed X tile
    __shared__ float sbase[GROWS * D_EMB];    // 4096 B memory terms
    __shared__ int   s_nbr[GROWS * KN];
    __shared__ int   s_eid[GROWS * KN];
    __shared__ float s_del[GROWS * KN];
    __shared__ float s_msk[GROWS * KN];
    __shared__ float s_inv[GROWS];
    __shared__ int   s_src[GROWS];

    const int t = threadIdx.x;
    const int m0 = blockIdx.x * GROWS;

    // ---- phase 0: metadata ----
    if (t < GROWS * KN) {
        const int row = t / KN;
        const int kk = t - row * KN;
        const int gb = m0 + row;
        const int nb = __ldg(&nbr[gb * KN + kk]);
        s_nbr[t] = nb;
        s_eid[t] = __ldg(&eidx[gb * KN + kk]);
        s_del[t] = __ldg(&ts[gb]) - __ldg(&ets[gb * KN + kk]);
        s_msk[t] = (nb != 0) ? 1.f : 0.f;
    }
    if (t >= 224 && t < 224 + GROWS) s_src[t - 224] = __ldg(&srcn[m0 + (t - 224)]);
    __syncthreads();
    if (t < GROWS) {
        float c = 0.f;
        #pragma unroll
        for (int k = 0; k < KN; k++) c += s_msk[t * KN + k];
        s_inv[t] = 1.f / fmaxf(c, 1.f);
    }
    __syncthreads();

    // ---- phase 1: task loop (gather/reduce into xs + sbase) ----
    for (int ti = t; ti < NTASKS; ti += TPB) {
        const int row = ti / TASKS_PER_ROW;
        const int tt = ti - row * TASKS_PER_ROW;
        const float inv = s_inv[row];
        const float* mk = &s_msk[row * KN];

        if (tt < 118) {
            // float4 gather-reduce
            const float* bp;
            int stride, colo, xoff;
            const int* rs;
            bool add_src, to_base = false;
            if (tt < 43)      { bp = nf;  stride = D_FEAT; colo = 4 * tt;        rs = &s_nbr[row * KN]; xoff = 0;      add_src = true; }
            else if (tt < 86) { bp = ef;  stride = D_FEAT; colo = 4 * (tt - 43); rs = &s_eid[row * KN]; xoff = D_FEAT; add_src = false; }
            else              { bp = mem; stride = D_EMB;  colo = 4 * (tt - 86); rs = &s_nbr[row * KN]; xoff = 0;      add_src = true; to_base = true; }

            float4 acc = make_float4(0.f, 0.f, 0.f, 0.f);
            #pragma unroll
            for (int k = 0; k < KN; k++) {
                const float m = mk[k];
                const float4 v = __ldg((const float4*)(bp + (size_t)rs[k] * stride + colo));
                acc.x = fmaf(m, v.x, acc.x);
                acc.y = fmaf(m, v.y, acc.y);
                acc.z = fmaf(m, v.z, acc.z);
                acc.w = fmaf(m, v.w, acc.w);
            }
            acc.x *= inv; acc.y *= inv; acc.z *= inv; acc.w *= inv;
            if (add_src) {
                const float4 sv = __ldg((const float4*)(bp + (size_t)s_src[row] * stride + colo));
                acc.x += sv.x; acc.y += sv.y; acc.z += sv.z; acc.w += sv.w;
            }
            if (to_base) {
                *(float4*)&sbase[row * D_EMB + colo] = acc;
            } else {
                const int c = xoff + colo;
                xs[(c + 0) * XS_ST + row] = acc.x;
                xs[(c + 1) * XS_ST + row] = acc.y;
                xs[(c + 2) * XS_ST + row] = acc.z;
                xs[(c + 3) * XS_ST + row] = acc.w;
            }
        } else if (tt < 218) {
            // time-encoding column
            const int j = tt - 118;
            const float wj = __ldg(&tw[j]);
            const float bj = __ldg(&tb[j]);
            const float* dl = &s_del[row * KN];
            float a = 0.f;
            #pragma unroll
            for (int k = 0; k < KN; k++) {
                float v = cos_cw(__fadd_rn(__fmul_rn(dl[k], wj), bj));
                a = fmaf(mk[k], v, a);
            }
            xs[(2 * D_FEAT + j) * XS_ST + row] = a * inv + cos_cw(bj);
        }
    }
    __syncthreads();

    // ---- phase 2: GEMM. col = t&127; rhalf = t>>7 -> rows 4*rhalf..4*rhalf+3 ----
    const int col = t & 127;
    const int r0 = (t >> 7) * 4;

    ull acc0 = 0ULL, acc1 = 0ULL;   // rows (r0,r0+1), (r0+2,r0+3)

    const float* Ws[3]   = { W_node, W_edge, W_time };
    const int    Klen[3] = { D_FEAT, D_FEAT, D_TIME };
    const int    Koff[3] = { 0, D_FEAT, 2 * D_FEAT };

    #pragma unroll
    for (int seg = 0; seg < 3; seg++) {
        const float* Wp = Ws[seg] + col;
        const int kl = Klen[seg];
        const int xo = Koff[seg];
        int kb = 0;
        #pragma unroll 1
        for (; kb + 8 <= kl; kb += 8) {
            float w[8];
            #pragma unroll
            for (int i = 0; i < 8; i++)
                w[i] = __ldg(Wp + (size_t)(kb + i) * D_EMB);
            #pragma unroll
            for (int i = 0; i < 8; i++) {
                const float* xk = &xs[(xo + kb + i) * XS_ST + r0];
                ull xA = *(const ull*)xk;         // broadcast LDS.64
                ull xB = *(const ull*)(xk + 2);   // broadcast LDS.64
                const ull w2 = dup2(w[i]);
                fma2(acc0, xA, w2);
                fma2(acc1, xB, w2);
            }
        }
        // tail (4 for each segment: 172%8=4, 100%8=4)
        #pragma unroll
        for (int i = 0; i < 4; i++) {
            const float wv = __ldg(Wp + (size_t)(kb + i) * D_EMB);
            const float* xk = &xs[(xo + kb + i) * XS_ST + r0];
            ull xA = *(const ull*)xk;
            ull xB = *(const ull*)(xk + 2);
            const ull w2 = dup2(wv);
            fma2(acc0, xA, w2);
            fma2(acc1, xB, w2);
        }
    }

    // ---- epilogue ----
    float v0, v1, v2, v3;
    unpack2(acc0, v0, v1);
    unpack2(acc1, v2, v3);
    out[(size_t)(m0 + r0 + 0) * D_EMB + col] = v0 + sbase[(r0 + 0) * D_EMB + col];
    out[(size_t)(m0 + r0 + 1) * D_EMB + col] = v1 + sbase[(r0 + 1) * D_EMB + col];
    out[(size_t)(m0 + r0 + 2) * D_EMB + col] = v2 + sbase[(r0 + 2) * D_EMB + col];
    out[(size_t)(m0 + r0 + 3) * D_EMB + col] = v3 + sbase[(r0 + 3) * D_EMB + col];
}

extern "C" void kernel_launch(void* const* d_in, const int* in_sizes, int n_in,
                              void* d_out, int out_size) {
    const float* node_features = (const float*)d_in[0];
    const float* edge_features = (const float*)d_in[1];
    const float* memory        = (const float*)d_in[2];
    const float* timestamps    = (const float*)d_in[3];
    const float* edge_times    = (const float*)d_in[4];
    const float* time_w        = (const float*)d_in[5];
    const float* time_b        = (const float*)d_in[6];
    const float* W_node        = (const float*)d_in[7];
    const float* W_edge        = (const float*)d_in[8];
    const float* W_time        = (const float*)d_in[9];
    const int*   source_nodes  = (const int*)d_in[10];
    const int*   neighbors     = (const int*)d_in[11];
    const int*   edge_idxs     = (const int*)d_in[12];
    float* out = (float*)d_out;

    fused_kernel<<<BN / GROWS, TPB>>>(node_features, edge_features, memory,
                                      timestamps, edge_times, time_w, time_b,
                                      source_nodes, neighbors, edge_idxs,
                                      W_node, W_edge, W_time, out);
}